// round 10
// baseline (speedup 1.0000x reference)
#include <cuda_runtime.h>
#include <math.h>
#include <stdint.h>

// x is (B, F) row-major fp32
#define B_ROWS 32768
#define F_COLS 1024
#define F4     (F_COLS / 4)            // 256 float4 per row
#define NBLK   512                     // contiguous 64-row slices, 4 CTAs/SM
#define ROWS_PER_CTA (B_ROWS / NBLK)   // 64
#define GROUP_ROWS 4                   // staging granularity (16 KB)
#define NGROUP (ROWS_PER_CTA / GROUP_ROWS)  // 16 (group 0 = SMEM stash)
#define EPS 1e-5f

// Scratch (allocations forbidden)
__device__ float g_psum[NBLK * F_COLS];   // (2 MB)
__device__ float g_psqr[NBLK * F_COLS];   // (2 MB)
__device__ float g_mean[F_COLS];
__device__ float g_rstd[F_COLS];

// Grid barrier (generation counter: replay-safe, wraparound-safe)
__device__ unsigned g_count = 0;
__device__ volatile unsigned g_gen = 0;

__device__ __forceinline__ void grid_barrier(unsigned nblocks) {
    __syncthreads();
    if (threadIdx.x == 0) {
        unsigned gen = g_gen;
        __threadfence();
        unsigned arrived = atomicAdd(&g_count, 1u) + 1u;
        if (arrived == nblocks) {
            atomicExch(&g_count, 0u);
            __threadfence();
            g_gen = gen + 1u;
        } else {
            while (g_gen == gen) { __nanosleep(64); }
        }
        __threadfence();
    }
    __syncthreads();
}

// Coherent L2 load for same-launch data (never __ldg: hoistable past barrier)
__device__ __forceinline__ float4 ldcg4(const float4* p) {
    float4 v;
    asm volatile("ld.global.cg.v4.f32 {%0,%1,%2,%3}, [%4];"
                 : "=f"(v.x), "=f"(v.y), "=f"(v.z), "=f"(v.w) : "l"(p));
    return v;
}

__device__ __forceinline__ uint32_t smem_u32(const void* p) {
    uint32_t a;
    asm("{ .reg .u64 t; cvta.to.shared.u64 t, %1; cvt.u32.u64 %0, t; }"
        : "=r"(a) : "l"(p));
    return a;
}

// ---------------------------------------------------------------------------
// Fused persistent kernel. Insight this round: phase-2b was STG.128-ISSUE
// bound (12 cyc/warp-instr => ~3 TB/s chip store ceiling). Replace per-thread
// global stores with TMA bulk stores: normalize into SMEM staging, one thread
// commits a 16 KB cp.async.bulk per 4-row group (double-buffered).
// ---------------------------------------------------------------------------
__global__ __launch_bounds__(256, 4) void msf_fused(const float* __restrict__ x,
                                                    const float* __restrict__ S_in,
                                                    float* __restrict__ out) {
    __shared__ float4 stage[2][GROUP_ROWS][256];   // 32 KB staging
    __shared__ float4 stash[GROUP_ROWS][256];      // 16 KB: rows 0..3 of slice
    // phase-2a reduction arrays alias the staging buffer (unused until 2b)
    float* sh_s = reinterpret_cast<float*>(&stage[0][0][0]);
    float* sh_q = sh_s + 256;

    const int bid = blockIdx.x;
    const int t = threadIdx.x;                    // column group 0..255
    const float4* __restrict__ x4 = reinterpret_cast<const float4*>(x);
    const size_t sbase = (size_t)bid * ROWS_PER_CTA * F4 + t;

    // ---------------- Phase 1: slice partials (+ stash rows 0..3) ----------
    {
        float4 s = make_float4(0.f, 0.f, 0.f, 0.f);
        float4 q = make_float4(0.f, 0.f, 0.f, 0.f);

#pragma unroll
        for (int g = 0; g < ROWS_PER_CTA / 8; ++g) {
            float4 v[8];
#pragma unroll
            for (int j = 0; j < 8; ++j)
                v[j] = __ldg(&x4[sbase + (size_t)(g * 8 + j) * F4]);
            if (g == 0) {
#pragma unroll
                for (int j = 0; j < GROUP_ROWS; ++j)
                    stash[j][t] = v[j];
            }
#pragma unroll
            for (int j = 0; j < 8; ++j) {
                s.x += v[j].x; s.y += v[j].y; s.z += v[j].z; s.w += v[j].w;
                q.x = fmaf(v[j].x, v[j].x, q.x);
                q.y = fmaf(v[j].y, v[j].y, q.y);
                q.z = fmaf(v[j].z, v[j].z, q.z);
                q.w = fmaf(v[j].w, v[j].w, q.w);
            }
        }
        __stcs(&reinterpret_cast<float4*>(g_psum)[bid * F4 + t], s);
        __stcs(&reinterpret_cast<float4*>(g_psqr)[bid * F4 + t], q);
    }

    grid_barrier(NBLK);

    // ---------------- Phase 2a: stats for my 2 columns ---------------------
    {
        const int half = t >> 7;
        const int tt = t & 127;
        const int col = bid * 2 + half;

        float s = 0.f, q = 0.f;
#pragma unroll
        for (int k = 0; k < NBLK / 128; ++k) {
            const int c = k * 128 + tt;
            s += __ldcg(&g_psum[c * F_COLS + col]);
            q += __ldcg(&g_psqr[c * F_COLS + col]);
        }
        sh_s[t] = s; sh_q[t] = q;
        __syncthreads();
#pragma unroll
        for (int w = 64; w > 0; w >>= 1) {
            if (tt < w) { sh_s[t] += sh_s[t + w]; sh_q[t] += sh_q[t + w]; }
            __syncthreads();
        }
        if (tt == 0) {
            const float n = (float)B_ROWS;
            float mean = sh_s[half << 7] / n;
            float m2 = sh_q[half << 7] - n * mean * mean + S_in[col];
            float var = m2 / (n - 1.0f);
            g_mean[col] = mean;
            g_rstd[col] = 1.0f / (sqrtf(var) + EPS);
        }
    }

    grid_barrier(NBLK);

    // ---------------- Phase 2b: normalize + TMA bulk stores ----------------
    {
        const float4 m = ldcg4(&reinterpret_cast<const float4*>(g_mean)[t]);
        const float4 r = ldcg4(&reinterpret_cast<const float4*>(g_rstd)[t]);
        char* const out_slice =
            reinterpret_cast<char*>(out) + (size_t)bid * ROWS_PER_CTA * 4096;

        float4 v[GROUP_ROWS], w[GROUP_ROWS];

#define LOADG(buf, g)                                                          \
        {                                                                      \
            const size_t hb = sbase + (size_t)((g) * GROUP_ROWS) * F4;         \
            _Pragma("unroll")                                                  \
            for (int j = 0; j < GROUP_ROWS; ++j)                               \
                buf[j] = __ldcs(&x4[hb + (size_t)j * F4]);                     \
        }
        // normalize buf -> staging[bi] -> one 16KB bulk store to group g
#define STAGE_STORE(buf, g, bi)                                                \
        {                                                                      \
            if (t == 0)                                                        \
                asm volatile("cp.async.bulk.wait_group.read 1;" ::: "memory"); \
            __syncthreads();       /* staging[bi] free for reuse */            \
            _Pragma("unroll")                                                  \
            for (int j = 0; j < GROUP_ROWS; ++j) {                             \
                float4 o;                                                      \
                o.x = (buf[j].x - m.x) * r.x;                                  \
                o.y = (buf[j].y - m.y) * r.y;                                  \
                o.z = (buf[j].z - m.z) * r.z;                                  \
                o.w = (buf[j].w - m.w) * r.w;                                  \
                stage[bi][j][t] = o;                                           \
            }                                                                  \
            asm volatile("fence.proxy.async.shared::cta;" ::: "memory");       \
            __syncthreads();                                                   \
            if (t == 0) {                                                      \
                uint32_t src = smem_u32(&stage[bi][0][0]);                     \
                char* dst = out_slice + (size_t)(g) * (GROUP_ROWS * 4096);     \
                asm volatile(                                                  \
                    "cp.async.bulk.global.shared::cta.bulk_group "             \
                    "[%0], [%1], %2;" :: "l"(dst), "r"(src),                   \
                    "r"(GROUP_ROWS * 4096) : "memory");                        \
                asm volatile("cp.async.bulk.commit_group;" ::: "memory");      \
            }                                                                  \
        }

        // Backward over gmem groups 15..1 (tail is L2/L1-hot from phase 1),
        // group 0 comes from the SMEM stash.
        LOADG(v, NGROUP - 1);
#pragma unroll
        for (int g = NGROUP - 1; g >= 3; g -= 2) {
            LOADG(w, g - 1);
            STAGE_STORE(v, g, 1);
            if (g >= 5) { LOADG(v, g - 2); }
            STAGE_STORE(w, g - 1, 0);
        }
        // g sequence covered: 15,14,...,4,3,2 ; v currently unused (g==3 path
        // loaded nothing new). Handle group 1 (gmem) and group 0 (stash).
        LOADG(v, 1);
        STAGE_STORE(v, 1, 1);
#pragma unroll
        for (int j = 0; j < GROUP_ROWS; ++j)
            w[j] = stash[j][t];
        STAGE_STORE(w, 0, 0);

        if (t == 0)
            asm volatile("cp.async.bulk.wait_group.read 0;" ::: "memory");
#undef LOADG
#undef STAGE_STORE
    }
}

extern "C" void kernel_launch(void* const* d_in, const int* in_sizes, int n_in,
                              void* d_out, int out_size) {
    const float* x    = (const float*)d_in[0];   // (32768, 1024) fp32
    // d_in[1] = running-mean buffer M: overwritten by first Welford sample -> unused
    const float* S_in = (const float*)d_in[2];   // (1024,) running M2, added into var
    float* out = (float*)d_out;

    msf_fused<<<NBLK, 256>>>(x, S_in, out);
}

// round 11
// speedup vs baseline: 1.0808x; 1.0808x over previous
#include <cuda_runtime.h>
#include <math.h>

// x is (B, F) row-major fp32
#define B_ROWS 32768
#define F_COLS 1024
#define F4     256                     // float4 per row
#define NBLK   512                     // contiguous 64-row slices
#define ROWS_PER_CTA 64
#define EPS 1e-5f

// Scratch (allocations forbidden)
__device__ float g_psum[NBLK * F_COLS];   // [slot][col] partial sums   (2 MB)
__device__ float g_psqr[NBLK * F_COLS];   // [slot][col] partial sumsq  (2 MB)
__device__ float g_mean[F_COLS];
__device__ float g_rstd[F_COLS];

// Sync state
__device__ unsigned g_count = 0;
__device__ volatile unsigned g_gen = 0;
__device__ unsigned g_done = 0;           // stats-published counter (per launch)

__device__ __forceinline__ void grid_barrier(unsigned nblocks) {
    __syncthreads();
    if (threadIdx.x == 0) {
        unsigned gen = g_gen;
        __threadfence();
        unsigned arrived = atomicAdd(&g_count, 1u) + 1u;
        if (arrived == nblocks) {
            atomicExch(&g_count, 0u);
            __threadfence();
            g_gen = gen + 1u;
        } else {
            while (g_gen == gen) { __nanosleep(64); }
        }
        __threadfence();
    }
    __syncthreads();
}

// Coherent L2 load for same-launch data (never __ldg: hoistable past barrier)
__device__ __forceinline__ float4 ldcg4(const float4* p) {
    float4 v;
    asm volatile("ld.global.cg.v4.f32 {%0,%1,%2,%3}, [%4];"
                 : "=f"(v.x), "=f"(v.y), "=f"(v.z), "=f"(v.w) : "l"(p));
    return v;
}

// ---------------------------------------------------------------------------
// Column-split pipelined persistent kernel. The write stream (~3.5 TB/s
// ceiling) is the binding constraint; this overlaps the half1 input read with
// the half0 output write so reads hide under the write-bound phase. Each
// column half is 64 MB -> reloads are guaranteed L2 hits.
// ---------------------------------------------------------------------------
__global__ __launch_bounds__(256, 4) void msf_fused(const float* __restrict__ x,
                                                    const float* __restrict__ S_in,
                                                    float* __restrict__ out) {
    __shared__ float4 sh4s[256];   // partial combine (4 KB)
    __shared__ float4 sh4q[256];   // (4 KB)
    __shared__ float sh_s[256];    // stats reduce (1 KB)
    __shared__ float sh_q[256];    // (1 KB)

    const int bid = blockIdx.x;
    const int t = threadIdx.x;
    const int tr = t >> 7;         // row parity 0/1
    const int tc = t & 127;        // float4 col within a half
    const float4* __restrict__ x4 = reinterpret_cast<const float4*>(x);
    float4* __restrict__ o4 = reinterpret_cast<float4*>(out);
    float4* g_psum4 = reinterpret_cast<float4*>(g_psum);
    float4* g_psqr4 = reinterpret_cast<float4*>(g_psqr);
    const size_t row0 = (size_t)bid * ROWS_PER_CTA;

    if (bid == 0 && t == 0) g_done = 0;   // all uses are after barrier 1

    float4 s = make_float4(0.f, 0.f, 0.f, 0.f);
    float4 q = make_float4(0.f, 0.f, 0.f, 0.f);

    // group g covers rows 8g..8g+7; this thread rows 8g+2j+tr, j=0..3
#define READ_GRP(g, hoff)                                                      \
    {                                                                          \
        float4 nv[4];                                                          \
        _Pragma("unroll")                                                      \
        for (int j = 0; j < 4; ++j)                                            \
            nv[j] = __ldg(&x4[(row0 + 8*(g) + 2*j + tr) * F4 + (hoff) + tc]);  \
        _Pragma("unroll")                                                      \
        for (int j = 0; j < 4; ++j) {                                          \
            s.x += nv[j].x; s.y += nv[j].y; s.z += nv[j].z; s.w += nv[j].w;    \
            q.x = fmaf(nv[j].x, nv[j].x, q.x);                                 \
            q.y = fmaf(nv[j].y, nv[j].y, q.y);                                 \
            q.z = fmaf(nv[j].z, nv[j].z, q.z);                                 \
            q.w = fmaf(nv[j].w, nv[j].w, q.w);                                 \
        }                                                                      \
    }
#define NORM_GRP(g, hoff, m, r)                                                \
    {                                                                          \
        float4 rv[4];                                                          \
        _Pragma("unroll")                                                      \
        for (int j = 0; j < 4; ++j)                                            \
            rv[j] = __ldcs(&x4[(row0 + 8*(g) + 2*j + tr) * F4 + (hoff) + tc]); \
        _Pragma("unroll")                                                      \
        for (int j = 0; j < 4; ++j) {                                          \
            float4 o;                                                          \
            o.x = (rv[j].x - m.x) * r.x;                                       \
            o.y = (rv[j].y - m.y) * r.y;                                       \
            o.z = (rv[j].z - m.z) * r.z;                                       \
            o.w = (rv[j].w - m.w) * r.w;                                       \
            __stcs(&o4[(row0 + 8*(g) + 2*j + tr) * F4 + (hoff) + tc], o);      \
        }                                                                      \
    }
    // combine the two row-parities and publish this CTA's partials
#define COMBINE_PARTIALS(hoff)                                                 \
    {                                                                          \
        sh4s[t] = s; sh4q[t] = q;                                              \
        __syncthreads();                                                       \
        if (t < 128) {                                                         \
            float4 a = sh4s[t], b = sh4s[t + 128];                             \
            a.x += b.x; a.y += b.y; a.z += b.z; a.w += b.w;                    \
            float4 c = sh4q[t], d = sh4q[t + 128];                             \
            c.x += d.x; c.y += d.y; c.z += d.z; c.w += d.w;                    \
            __stcs(&g_psum4[bid * F4 + (hoff) + t], a);                        \
            __stcs(&g_psqr4[bid * F4 + (hoff) + t], c);                        \
        }                                                                      \
        __syncthreads();                                                       \
        s = make_float4(0.f, 0.f, 0.f, 0.f);                                   \
        q = make_float4(0.f, 0.f, 0.f, 0.f);                                   \
    }

    // ---------------- Phase A: read half0, partials ------------------------
#pragma unroll
    for (int g = 0; g < 8; ++g) READ_GRP(g, 0)
    COMBINE_PARTIALS(0)

    grid_barrier(NBLK);

    // ---------------- Phase C -----------------------------------------------
    // (1) stats for my column (half0: col = bid), publish via fenced counter
    {
        const int col = bid;
        float ps = __ldcg(&g_psum[(size_t)t * F_COLS + col])
                 + __ldcg(&g_psum[(size_t)(t + 256) * F_COLS + col]);
        float pq = __ldcg(&g_psqr[(size_t)t * F_COLS + col])
                 + __ldcg(&g_psqr[(size_t)(t + 256) * F_COLS + col]);
        sh_s[t] = ps; sh_q[t] = pq;
        __syncthreads();
#pragma unroll
        for (int w = 128; w > 0; w >>= 1) {
            if (t < w) { sh_s[t] += sh_s[t + w]; sh_q[t] += sh_q[t + w]; }
            __syncthreads();
        }
        if (t == 0) {
            const float n = (float)B_ROWS;
            float mean = sh_s[0] / n;
            float m2 = sh_q[0] - n * mean * mean + S_in[col];
            g_mean[col] = mean;
            g_rstd[col] = 1.0f / (sqrtf(m2 / (n - 1.0f)) + EPS);
            __threadfence();
            atomicAdd(&g_done, 1u);
        }
    }

    // (2) read-ahead half1 rows 0..31 (hides other CTAs' stats latency)
#pragma unroll
    for (int g = 0; g < 4; ++g) READ_GRP(g, 128)

    // (3) wait until all 512 half0 columns are published
    if (t == 0) {
        while (__ldcg(&g_done) < NBLK) { __nanosleep(32); }
    }
    __syncthreads();

    {
        const float4 m = ldcg4(&reinterpret_cast<const float4*>(g_mean)[tc]);
        const float4 r = ldcg4(&reinterpret_cast<const float4*>(g_rstd)[tc]);

        // (4) interleave: read half1 rows 32..63 with write half0 rows 0..31
#pragma unroll
        for (int g = 4; g < 8; ++g) {
            READ_GRP(g, 128)
            NORM_GRP(g - 4, 0, m, r)
        }
        // (5) write half0 rows 32..63
#pragma unroll
        for (int g = 4; g < 8; ++g) NORM_GRP(g, 0, m, r)
    }
    COMBINE_PARTIALS(128)

    grid_barrier(NBLK);

    // ---------------- Phase E: stats + normalize half1 ---------------------
    {
        const int col = F_COLS / 2 + bid;
        float ps = __ldcg(&g_psum[(size_t)t * F_COLS + col])
                 + __ldcg(&g_psum[(size_t)(t + 256) * F_COLS + col]);
        float pq = __ldcg(&g_psqr[(size_t)t * F_COLS + col])
                 + __ldcg(&g_psqr[(size_t)(t + 256) * F_COLS + col]);
        sh_s[t] = ps; sh_q[t] = pq;
        __syncthreads();
#pragma unroll
        for (int w = 128; w > 0; w >>= 1) {
            if (t < w) { sh_s[t] += sh_s[t + w]; sh_q[t] += sh_q[t + w]; }
            __syncthreads();
        }
        if (t == 0) {
            const float n = (float)B_ROWS;
            float mean = sh_s[0] / n;
            float m2 = sh_q[0] - n * mean * mean + S_in[col];
            g_mean[col] = mean;
            g_rstd[col] = 1.0f / (sqrtf(m2 / (n - 1.0f)) + EPS);
            __threadfence();
            atomicAdd(&g_done, 1u);
        }
    }
    if (t == 0) {
        while (__ldcg(&g_done) < 2 * NBLK) { __nanosleep(32); }
    }
    __syncthreads();
    {
        const float4 m = ldcg4(&reinterpret_cast<const float4*>(g_mean)[128 + tc]);
        const float4 r = ldcg4(&reinterpret_cast<const float4*>(g_rstd)[128 + tc]);
#pragma unroll
        for (int g = 0; g < 8; ++g) NORM_GRP(g, 128, m, r)
    }
#undef READ_GRP
#undef NORM_GRP
#undef COMBINE_PARTIALS
}

extern "C" void kernel_launch(void* const* d_in, const int* in_sizes, int n_in,
                              void* d_out, int out_size) {
    const float* x    = (const float*)d_in[0];   // (32768, 1024) fp32
    // d_in[1] = running-mean buffer M: overwritten by first Welford sample -> unused
    const float* S_in = (const float*)d_in[2];   // (1024,) running M2, added into var
    float* out = (float*)d_out;

    msf_fused<<<NBLK, 256>>>(x, S_in, out);
}

// round 13
// speedup vs baseline: 1.0818x; 1.0009x over previous
#include <cuda_runtime.h>
#include <math.h>

// x is (B, F) row-major fp32
#define B_ROWS 32768
#define F_COLS 1024
#define F4     256                     // float4 per row
#define NBLK   512                     // contiguous 64-row slices, 4 CTAs/SM
#define ROWS_PER_CTA 64
#define STASH_ROWS 11                  // rows 0..10 in SMEM (45 KB, <48 KB static)
#define GRP0_ROW 12                    // groups cover rows 12..63 (13 groups of 4)
#define NGRP 13
#define EPS 1e-5f

// Scratch (allocations forbidden)
__device__ float g_psum[NBLK * F_COLS];   // (2 MB)
__device__ float g_psqr[NBLK * F_COLS];   // (2 MB)
__device__ float g_mean[F_COLS];
__device__ float g_rstd[F_COLS];

// Sync state
__device__ unsigned g_count = 0;
__device__ volatile unsigned g_gen = 0;
__device__ unsigned g_done = 0;

__device__ __forceinline__ void grid_barrier(unsigned nblocks) {
    __syncthreads();
    if (threadIdx.x == 0) {
        unsigned gen = g_gen;
        __threadfence();
        unsigned arrived = atomicAdd(&g_count, 1u) + 1u;
        if (arrived == nblocks) {
            atomicExch(&g_count, 0u);
            __threadfence();
            g_gen = gen + 1u;
        } else {
            while (g_gen == gen) { __nanosleep(64); }
        }
        __threadfence();
    }
    __syncthreads();
}

// Coherent L2 load for same-launch data (never __ldg: hoistable past barrier)
__device__ __forceinline__ float4 ldcg4(const float4* p) {
    float4 v;
    asm volatile("ld.global.cg.v4.f32 {%0,%1,%2,%3}, [%4];"
                 : "=f"(v.x), "=f"(v.y), "=f"(v.z), "=f"(v.w) : "l"(p));
    return v;
}

// ---------------------------------------------------------------------------
// LTS-minimizing fused persistent kernel. L2 hits cost LTS bandwidth like
// misses, so the phase-2b re-read is served from SMEM (stash, LTS-free) and
// L1 (backward order over freshly-read tail) wherever possible. Barrier 2 is
// replaced by a done-counter (TWO publications per CTA -> wait for 2*NBLK!)
// whose wait is hidden under prefetched loads.
// ---------------------------------------------------------------------------
__global__ __launch_bounds__(256, 4) void msf_fused(const float* __restrict__ x,
                                                    const float* __restrict__ S_in,
                                                    float* __restrict__ out) {
    __shared__ float4 stash[STASH_ROWS][256];     // 45056 B
    __shared__ float sh_s[256];                   // 1 KB
    __shared__ float sh_q[256];                   // 1 KB

    const int bid = blockIdx.x;
    const int t = threadIdx.x;                    // column group 0..255
    const float4* __restrict__ x4 = reinterpret_cast<const float4*>(x);
    float4* __restrict__ o4 = reinterpret_cast<float4*>(out);
    const size_t sbase = (size_t)bid * ROWS_PER_CTA * F4 + t;

    if (bid == 0 && t == 0) g_done = 0;           // increments happen post-barrier

    // ---------------- Phase 1: slice partials (+ stash rows 0..10) ---------
    {
        float4 s = make_float4(0.f, 0.f, 0.f, 0.f);
        float4 q = make_float4(0.f, 0.f, 0.f, 0.f);

#pragma unroll
        for (int g = 0; g < ROWS_PER_CTA / 8; ++g) {
            float4 v[8];
#pragma unroll
            for (int j = 0; j < 8; ++j)
                v[j] = __ldg(&x4[sbase + (size_t)(g * 8 + j) * F4]);
#pragma unroll
            for (int j = 0; j < 8; ++j) {
                const int row = g * 8 + j;
                if (row < STASH_ROWS) stash[row][t] = v[j];   // compile-time
            }
#pragma unroll
            for (int j = 0; j < 8; ++j) {
                s.x += v[j].x; s.y += v[j].y; s.z += v[j].z; s.w += v[j].w;
                q.x = fmaf(v[j].x, v[j].x, q.x);
                q.y = fmaf(v[j].y, v[j].y, q.y);
                q.z = fmaf(v[j].z, v[j].z, q.z);
                q.w = fmaf(v[j].w, v[j].w, q.w);
            }
        }
        __stcs(&reinterpret_cast<float4*>(g_psum)[bid * F4 + t], s);
        __stcs(&reinterpret_cast<float4*>(g_psqr)[bid * F4 + t], q);
    }

    grid_barrier(NBLK);

    // ---------------- Phase 2a: stats for my 2 columns, publish ------------
    {
        const int half = t >> 7;
        const int tt = t & 127;
        const int col = bid * 2 + half;

        float s = 0.f, q = 0.f;
#pragma unroll
        for (int k = 0; k < NBLK / 128; ++k) {
            const int c = k * 128 + tt;
            s += __ldcg(&g_psum[c * F_COLS + col]);
            q += __ldcg(&g_psqr[c * F_COLS + col]);
        }
        sh_s[t] = s; sh_q[t] = q;
        __syncthreads();
#pragma unroll
        for (int w = 64; w > 0; w >>= 1) {
            if (tt < w) { sh_s[t] += sh_s[t + w]; sh_q[t] += sh_q[t + w]; }
            __syncthreads();
        }
        if (tt == 0) {                                 // t==0 AND t==128 publish
            const float n = (float)B_ROWS;
            float mean = sh_s[half << 7] / n;
            float m2 = sh_q[half << 7] - n * mean * mean + S_in[col];
            g_mean[col] = mean;
            g_rstd[col] = 1.0f / (sqrtf(m2 / (n - 1.0f)) + EPS);
            __threadfence();
            atomicAdd(&g_done, 1u);
        }
    }

    // ---------------- Phase 2b: normalize ----------------------------------
    {
        float4 a[4], b[4], v11;

        // group i covers rows GRP0_ROW+4i .. +3, i = 0..12 (backward walk)
#define LOADG(buf, i)                                                          \
        {                                                                      \
            const size_t hb = sbase + (size_t)(GRP0_ROW + (i) * 4) * F4;       \
            _Pragma("unroll")                                                  \
            for (int j = 0; j < 4; ++j)                                        \
                buf[j] = __ldcs(&x4[hb + (size_t)j * F4]);                     \
        }
#define STOREG(buf, i)                                                         \
        {                                                                      \
            const size_t hb = sbase + (size_t)(GRP0_ROW + (i) * 4) * F4;       \
            _Pragma("unroll")                                                  \
            for (int j = 0; j < 4; ++j) {                                      \
                float4 o;                                                      \
                o.x = (buf[j].x - m.x) * r.x;                                  \
                o.y = (buf[j].y - m.y) * r.y;                                  \
                o.z = (buf[j].z - m.z) * r.z;                                  \
                o.w = (buf[j].w - m.w) * r.w;                                  \
                __stcs(&o4[hb + (size_t)j * F4], o);                           \
            }                                                                  \
        }

        // Prefetch (independent of stats) -> hides done-counter wait
        LOADG(a, NGRP - 1)                         // rows 60..63 (L1-hot)
        LOADG(b, NGRP - 2)                         // rows 56..59
        v11 = __ldcs(&x4[sbase + (size_t)11 * F4]);

        // FIX (R12 bug): 2 publications per CTA -> 2*NBLK total columns.
        if (t == 0) {
            while (__ldcg(&g_done) < 2u * NBLK) { __nanosleep(32); }
        }
        __syncthreads();
        __threadfence();

        const float4 m = ldcg4(&reinterpret_cast<const float4*>(g_mean)[t]);
        const float4 r = ldcg4(&reinterpret_cast<const float4*>(g_rstd)[t]);

        // standalone row 11
        {
            float4 o;
            o.x = (v11.x - m.x) * r.x;
            o.y = (v11.y - m.y) * r.y;
            o.z = (v11.z - m.z) * r.z;
            o.w = (v11.w - m.w) * r.w;
            __stcs(&o4[sbase + (size_t)11 * F4], o);
        }

        // 13 groups backward, 2-buffer rotation
#pragma unroll
        for (int k = 0; k < NGRP; ++k) {
            const int i = NGRP - 1 - k;            // 12..0
            if ((k & 1) == 0) {
                STOREG(a, i)
                if (i >= 2) LOADG(a, i - 2)
            } else {
                STOREG(b, i)
                if (i >= 2) LOADG(b, i - 2)
            }
        }
#undef LOADG
#undef STOREG

        // rows 10..0 from the SMEM stash (zero LTS read traffic)
#pragma unroll
        for (int row = STASH_ROWS - 1; row >= 0; --row) {
            float4 v = stash[row][t];
            float4 o;
            o.x = (v.x - m.x) * r.x;
            o.y = (v.y - m.y) * r.y;
            o.z = (v.z - m.z) * r.z;
            o.w = (v.w - m.w) * r.w;
            __stcs(&o4[sbase + (size_t)row * F4], o);
        }
    }
}

extern "C" void kernel_launch(void* const* d_in, const int* in_sizes, int n_in,
                              void* d_out, int out_size) {
    const float* x    = (const float*)d_in[0];   // (32768, 1024) fp32
    // d_in[1] = running-mean buffer M: overwritten by first Welford sample -> unused
    const float* S_in = (const float*)d_in[2];   // (1024,) running M2, added into var
    float* out = (float*)d_out;

    msf_fused<<<NBLK, 256>>>(x, S_in, out);
}